// round 5
// baseline (speedup 1.0000x reference)
#include <cuda_runtime.h>
#include <math.h>

#define TT 256
#define BB 64
#define DD 1024
#define ND (3*DD)        // 3072
#define MTOT (TT*BB)     // 16384

#define RG 64            // GRU CTAs
#define HELPERS 84       // xproj helper CTAs
#define GRID_ALL (RG + HELPERS)
#define NTILE_N (ND / 128)        // 24
#define NTILE_M (MTOT / 128)      // 128

#define NTHREADS 384

// ---------------- scratch ----------------
__device__ float g_xproj[(size_t)MTOT * ND];
__device__ float g_heff[2][BB * DD];
__device__ unsigned g_count;
__device__ unsigned g_release;
__device__ unsigned g_tilecnt[NTILE_M];

// ---------------- helpers ----------------
__device__ __forceinline__ unsigned f2tf(float x) {
    unsigned y;
    asm("cvt.rna.tf32.f32 %0, %1;" : "=r"(y) : "f"(x));
    return y;
}
__device__ __forceinline__ float f2tf_f(float x) { return __uint_as_float(f2tf(x)); }
__device__ __forceinline__ unsigned fu(float x) { return __float_as_uint(x); }

__device__ __forceinline__ void mma_tf32(float c[4], const unsigned a[4], const unsigned b[2]) {
    asm volatile(
        "mma.sync.aligned.m16n8k8.row.col.f32.tf32.tf32.f32 "
        "{%0,%1,%2,%3}, {%4,%5,%6,%7}, {%8,%9}, {%0,%1,%2,%3};\n"
        : "+f"(c[0]), "+f"(c[1]), "+f"(c[2]), "+f"(c[3])
        : "r"(a[0]), "r"(a[1]), "r"(a[2]), "r"(a[3]),
          "r"(b[0]), "r"(b[1]));
}

__device__ __forceinline__ bool get_done(const void* p, int idx, int flag) {
    if (flag == 1) return ((const unsigned char*)p)[idx] != 0;
    if (flag == 0) return ((const int*)p)[idx] != 0;
    return ((const float*)p)[idx] != 0.0f;
}

__device__ __forceinline__ float sigmoidf_(float x) {
    return 1.0f / (1.0f + __expf(-x));
}

// ---------------- reset ----------------
__global__ void reset_kernel() {
    int t = threadIdx.x;
    if (t == 0) { g_count = 0u; g_release = 0u; }
    if (t < NTILE_M) g_tilecnt[t] = 0u;
}

// ---------------- geometry ----------------
#define AK 32
#define AS_S 36
#define BS_S 132
#define RKC 64
#define FPC 16

// GRU smem (words):
//   wsF : 128 kkg x 6 (wn*2+nt) x 32 lanes x 2  = 49152 words (b-fragments, float2/lane)
//   bufA/bufB : 8 kk-blocks, kk stride 516 (512 + 4-word skew), last block ends 4124 -> 4128
#define WS_WORDS 49152
#define KSTR 516
#define BUF_WORDS 4128
#define OFF_BUFA WS_WORDS
#define OFF_BUFB (WS_WORDS + BUF_WORDS)
#define OFF_BH   (WS_WORDS + 2 * BUF_WORDS)      // 16 words for bhn
#define GRU_SMEM_BYTES ((OFF_BH + 16) * 4)       // 229,696 B
#define PS_S 50                                   // ps unions into bufA

__device__ __forceinline__ void grid_barrier(unsigned expected) {
    __syncthreads();
    if (threadIdx.x == 0) {
        __threadfence();
        unsigned prev = atomicAdd(&g_count, 1u);
        if (prev + 1u == expected) {
            atomicExch(&g_release, expected);
        } else {
            const volatile unsigned* rp = (const volatile unsigned*)&g_release;
            while (*rp < expected) { }
        }
        __threadfence();
    }
    __syncthreads();
}

// ---------------- helper path: xproj tiles (8 active warps of 12) ----------------
__device__ void helper_xproj(float* sm, const float* __restrict__ ins,
                             const float* __restrict__ Wi,
                             const float* __restrict__ bi, int hid)
{
    float* As = sm;
    float* Bs = sm + 128 * AS_S;

    int tid  = threadIdx.x;
    int warp = tid >> 5, lane = tid & 31;
    int wm = warp >> 2, wn = warp & 3;       // valid for warp < 8
    int g = lane >> 2, tg = lane & 3;
    int ra = tid >> 3;
    int ca = (tid & 7) << 2;
    int rb = tid >> 5;
    int cb = (tid & 31) << 2;
    bool stager = (tid < 256);
    bool mmaer = (warp < 8);

    for (int tile = hid; tile < NTILE_M * NTILE_N; tile += HELPERS) {
        int mb = tile / NTILE_N, nb = tile % NTILE_N;
        int mBase = mb * 128, nBase = nb * 128;

        float acc[4][4][4];
#pragma unroll
        for (int mt = 0; mt < 4; mt++)
#pragma unroll
            for (int nt = 0; nt < 4; nt++)
#pragma unroll
                for (int i = 0; i < 4; i++) acc[mt][nt][i] = 0.0f;

        float4 av[4], bv[4];
        if (stager) {
#pragma unroll
            for (int p = 0; p < 4; p++)
                av[p] = *(const float4*)&ins[(size_t)(mBase + ra + p * 32) * DD + ca];
#pragma unroll
            for (int p = 0; p < 4; p++)
                bv[p] = *(const float4*)&Wi[(size_t)(rb + p * 8) * ND + nBase + cb];
        }

        for (int kb = 0; kb < DD; kb += AK) {
            if (stager) {
#pragma unroll
                for (int p = 0; p < 4; p++) {
                    float* d = &As[(ra + p * 32) * AS_S + ca];
                    d[0] = f2tf_f(av[p].x); d[1] = f2tf_f(av[p].y);
                    d[2] = f2tf_f(av[p].z); d[3] = f2tf_f(av[p].w);
                }
#pragma unroll
                for (int p = 0; p < 4; p++) {
                    float* d = &Bs[(rb + p * 8) * BS_S + cb];
                    d[0] = f2tf_f(bv[p].x); d[1] = f2tf_f(bv[p].y);
                    d[2] = f2tf_f(bv[p].z); d[3] = f2tf_f(bv[p].w);
                }
            }
            __syncthreads();

            if (stager && kb + AK < DD) {
#pragma unroll
                for (int p = 0; p < 4; p++)
                    av[p] = *(const float4*)&ins[(size_t)(mBase + ra + p * 32) * DD + kb + AK + ca];
#pragma unroll
                for (int p = 0; p < 4; p++)
                    bv[p] = *(const float4*)&Wi[(size_t)(kb + AK + rb + p * 8) * ND + nBase + cb];
            }

            if (mmaer) {
#pragma unroll
                for (int kk = 0; kk < AK; kk += 8) {
                    unsigned a[4][4];
#pragma unroll
                    for (int mt = 0; mt < 4; mt++) {
                        int r0 = wm * 64 + mt * 16;
                        a[mt][0] = fu(As[(r0 + g) * AS_S + kk + tg]);
                        a[mt][1] = fu(As[(r0 + 8 + g) * AS_S + kk + tg]);
                        a[mt][2] = fu(As[(r0 + g) * AS_S + kk + 4 + tg]);
                        a[mt][3] = fu(As[(r0 + 8 + g) * AS_S + kk + 4 + tg]);
                    }
                    unsigned b[4][2];
#pragma unroll
                    for (int nt = 0; nt < 4; nt++) {
                        int c0 = wn * 32 + nt * 8;
                        b[nt][0] = fu(Bs[(kk + tg) * BS_S + c0 + g]);
                        b[nt][1] = fu(Bs[(kk + 4 + tg) * BS_S + c0 + g]);
                    }
#pragma unroll
                    for (int mt = 0; mt < 4; mt++)
#pragma unroll
                        for (int nt = 0; nt < 4; nt++)
                            mma_tf32(acc[mt][nt], a[mt], b[nt]);
                }
            }
            __syncthreads();
        }

        if (mmaer) {
#pragma unroll
            for (int mt = 0; mt < 4; mt++) {
#pragma unroll
                for (int nt = 0; nt < 4; nt++) {
                    int col = nBase + wn * 32 + nt * 8 + 2 * tg;
                    float b0 = bi[col], b1 = bi[col + 1];
                    int r0 = mBase + wm * 64 + mt * 16 + g;
                    float2 v0 = make_float2(acc[mt][nt][0] + b0, acc[mt][nt][1] + b1);
                    float2 v1 = make_float2(acc[mt][nt][2] + b0, acc[mt][nt][3] + b1);
                    *(float2*)&g_xproj[(size_t)r0 * ND + col] = v0;
                    *(float2*)&g_xproj[(size_t)(r0 + 8) * ND + col] = v1;
                }
            }
        }
        __threadfence();
        __syncthreads();
        if (tid == 0) atomicAdd(&g_tilecnt[mb], 1u);
    }
}

// ---------------- fused persistent kernel ----------------
__global__ __launch_bounds__(NTHREADS) void fused_kernel(
    const float* __restrict__ ins, const float* __restrict__ hiddens,
    const void* __restrict__ dones, const float* __restrict__ init_carry,
    const float* __restrict__ Wi, const float* __restrict__ Wh,
    const float* __restrict__ bi, const float* __restrict__ bhn,
    float* __restrict__ out)
{
    extern __shared__ float sm[];
    int bid = blockIdx.x;
    if (bid >= RG) { helper_xproj(sm, ins, Wi, bi, bid - RG); return; }

    float* ws   = sm;                 // b-fragments
    float* bufA = &sm[OFF_BUFA];
    float* bufB = &sm[OFF_BUFB];
    float* ps   = &sm[OFF_BUFA];      // union with bufA
    float* bh_s = &sm[OFF_BH];

    int tid = threadIdx.x;
    int f0 = bid * FPC;

    int warp = tid >> 5, lane = tid & 31;
    int wm = warp & 3, wn = warp >> 2;      // wn 0..2
    int lane4 = lane * 4, lane2 = lane * 2;

    // dones-dtype detection
    int dflag;
    {
        int lf = 0, li = 0;
        const float* pf = (const float*)dones;
        const int*   pi = (const int*)dones;
        for (int i = lane; i < 256; i += 32) {
            float v = pf[i];
            if (!(v == 0.0f || v == 1.0f)) lf = 1;
            int w = pi[i];
            if (!(w == 0 || w == 1)) li = 1;
        }
        lf = __any_sync(0xffffffffu, lf);
        li = __any_sync(0xffffffffu, li);
        dflag = (!lf) ? 2 : ((!li) ? 0 : 1);
    }

    // one-time: W_h slice as fragment-major float2 per lane
    // wsF[((kkg*6 + wn*2+nt)*32 + lane)*2 + {0,1}] = Wh[(kkg*8+tg[+4])*ND + gate*DD + f0 + j]
    for (int idx = tid; idx < 128 * 6 * 32; idx += NTHREADS) {
        int l = idx & 31;
        int ntwn = (idx >> 5) % 6;
        int kkg = idx / 192;
        int gg = l >> 2, tg2 = l & 3;
        int c = (ntwn >> 1) * 16 + (ntwn & 1) * 8 + gg;   // 0..47
        int gate = c >> 4, j = c & 15;
        size_t colg = (size_t)gate * DD + f0 + j;
        int k0 = kkg * 8 + tg2;
        float v0 = Wh[(size_t)k0 * ND + colg];
        float v1 = Wh[(size_t)(k0 + 4) * ND + colg];
        ws[(size_t)idx * 2 + 0] = f2tf_f(v0);
        ws[(size_t)idx * 2 + 1] = f2tf_f(v1);
    }
    if (tid < 16) bh_s[tid] = bhn[f0 + tid];

    // prologue: h_eff[0]
    for (int e = tid; e < BB * FPC; e += NTHREADS) {
        int b = e >> 4, j = e & 15;
        int f = f0 + j;
        bool dn = get_done(dones, b, dflag);
        float v = dn ? hiddens[(size_t)b * DD + f] : init_carry[(size_t)b * DD + f];
        g_heff[0][b * DD + f] = v;
    }
    __syncthreads();
    unsigned bar_no = 1;
    grid_barrier(RG * bar_no); bar_no++;

    // staging precompute: thread handles elements e = tid + i*384 (i<3; i=2 only tid<256)
    int nst = (tid < 256) ? 3 : 2;
    int gofs[3];   // gmem float4 offset (row*DD + c) within chunk
    int sofs[3];   // smem fragment word offset W (add tg*4 per component)
#pragma unroll
    for (int i = 0; i < 3; i++) {
        int e = tid + i * NTHREADS;
        if (e >= 1024) e = 1023;                 // dummy safe
        int r = e >> 4, c = (e & 15) << 2;
        gofs[i] = r * DD + c;
        int wmr = r >> 4, gg = r & 7, half = (r >> 3) & 1;
        int kk = c >> 3, sub = (c >> 2) & 1;
        sofs[i] = kk * KSTR + wmr * 128 + 16 * gg + (half + 2 * sub);
    }

#define LOADC(dst, cidx) { \
    _Pragma("unroll") \
    for (int i = 0; i < 3; i++) if (i < nst) \
        dst[i] = *(const float4*)&hsrc[gofs[i] + (cidx) * RKC]; }
#define COMMIT(src, bufp) { \
    _Pragma("unroll") \
    for (int i = 0; i < 3; i++) if (i < nst) { \
        float* d = &(bufp)[sofs[i]]; \
        d[0]  = f2tf_f(src[i].x); d[4]  = f2tf_f(src[i].y); \
        d[8]  = f2tf_f(src[i].z); d[12] = f2tf_f(src[i].w); } }

    for (int t = 0; t < TT; t++) {
        const float* hsrc = g_heff[t & 1];

        float acc[2][4];
#pragma unroll
        for (int nt = 0; nt < 2; nt++)
#pragma unroll
            for (int i = 0; i < 4; i++) acc[nt][i] = 0.0f;

        float4 pv0[3], pv1[3];
        LOADC(pv0, 0);
        LOADC(pv1, 1);

        // xproj tile availability
        if ((t & 1) == 0) {
            if (tid == 0) {
                const volatile unsigned* tp = (const volatile unsigned*)&g_tilecnt[t >> 1];
                while (*tp < (unsigned)NTILE_N) { }
                __threadfence();
            }
            __syncthreads();
        }

        // epilogue operand prefetch
        float xr[3], xz[3], xn[3], he[3], hv[3];
        int dnp[3];
#pragma unroll
        for (int i = 0; i < 3; i++) {
            int e = tid + i * NTHREADS;
            if (e < 1024) {
                int b = e >> 4, j = e & 15;
                int f = f0 + j;
                const float* xb = &g_xproj[((size_t)t * BB + b) * ND];
                xr[i] = xb[f]; xz[i] = xb[DD + f]; xn[i] = xb[2 * DD + f];
                he[i] = hsrc[b * DD + f];
                if (t < TT - 1) {
                    dnp[i] = get_done(dones, (t + 1) * BB + b, dflag) ? 1 : 0;
                    hv[i] = hiddens[((size_t)(t + 1) * BB + b) * DD + f];
                } else { dnp[i] = 0; hv[i] = 0.0f; }
            }
        }

        COMMIT(pv0, bufA);
        LOADC(pv0, 2);
        __syncthreads();

        for (int kb = 0; kb < 16; kb++) {
            float* cbuf = (kb & 1) ? bufB : bufA;
            if (kb + 1 < 16) {
                if (kb & 1) { COMMIT(pv0, bufA); if (kb + 3 < 16) LOADC(pv0, kb + 3); }
                else        { COMMIT(pv1, bufB); if (kb + 3 < 16) LOADC(pv1, kb + 3); }
            }
            int kg0 = kb * 8;
#pragma unroll
            for (int kk = 0; kk < 8; kk++) {
                float4 a4 = *(const float4*)&cbuf[kk * KSTR + wm * 128 + lane4];
#pragma unroll
                for (int nt = 0; nt < 2; nt++) {
                    float2 b2 = *(const float2*)&ws[(size_t)((kg0 + kk) * 6 + wn * 2 + nt) * 64 + lane2];
                    mma_tf32(acc[nt], (const unsigned*)&a4, (const unsigned*)&b2);
                }
            }
            __syncthreads();
        }

        // GEMM result -> ps
        {
            int g = lane >> 2, tg = lane & 3;
            int r0 = wm * 16 + g;
#pragma unroll
            for (int nt = 0; nt < 2; nt++) {
                int c0 = wn * 16 + nt * 8 + 2 * tg;
                ps[r0 * PS_S + c0]           = acc[nt][0];
                ps[r0 * PS_S + c0 + 1]       = acc[nt][1];
                ps[(r0 + 8) * PS_S + c0]     = acc[nt][2];
                ps[(r0 + 8) * PS_S + c0 + 1] = acc[nt][3];
            }
        }
        __syncthreads();

        // gates + update
#pragma unroll
        for (int i = 0; i < 3; i++) {
            int e = tid + i * NTHREADS;
            if (e < 1024) {
                int b = e >> 4, j = e & 15;
                int f = f0 + j;
                float r = sigmoidf_(xr[i] + ps[b * PS_S + j]);
                float z = sigmoidf_(xz[i] + ps[b * PS_S + 16 + j]);
                float n = tanhf(xn[i] + r * (ps[b * PS_S + 32 + j] + bh_s[j]));
                float hnew = (1.0f - z) * n + z * he[i];
                out[BB * DD + ((size_t)t * BB + b) * DD + f] = hnew;   // ys
                if (t == TT - 1) {
                    out[(size_t)b * DD + f] = hnew;                     // final_carry
                } else {
                    float nv = dnp[i] ? hv[i] : hnew;
                    g_heff[(t & 1) ^ 1][b * DD + f] = nv;
                }
            }
        }

        grid_barrier(RG * bar_no); bar_no++;
    }
#undef LOADC
#undef COMMIT
}

// ---------------- launch ----------------
extern "C" void kernel_launch(void* const* d_in, const int* in_sizes, int n_in,
                              void* d_out, int out_size) {
    const float* ins        = (const float*)d_in[0];
    const float* hiddens    = (const float*)d_in[1];
    const void*  dones      = (const void*)d_in[2];
    const float* init_carry = (const float*)d_in[3];
    const float* Wi         = (const float*)d_in[4];
    const float* Wh         = (const float*)d_in[5];
    const float* bi         = (const float*)d_in[6];
    const float* bhn        = (const float*)d_in[7];
    float* out = (float*)d_out;

    static int smem_set = 0;
    if (!smem_set) {
        cudaFuncSetAttribute(fused_kernel,
            cudaFuncAttributeMaxDynamicSharedMemorySize, GRU_SMEM_BYTES);
        smem_set = 1;
    }

    reset_kernel<<<1, 128>>>();
    fused_kernel<<<GRID_ALL, NTHREADS, GRU_SMEM_BYTES>>>(
        ins, hiddens, dones, init_carry, Wi, Wh, bi, bhn, out);
}